// round 14
// baseline (speedup 1.0000x reference)
#include <cuda_runtime.h>
#include <math.h>
#include <cstdint>

#define NT 128
#define BC 32
typedef unsigned long long ull;

#define FMA2(d, a, b, c) \
    asm("fma.rn.f32x2 %0, %1, %2, %3;" : "=l"(d) : "l"(a), "l"(b), "l"(c))
#define PACK2(d, lo, hi) \
    asm("mov.b64 %0, {%1, %2};" : "=l"(d) : "f"(lo), "f"(hi))
#define UNPACK2(lo, hi, v) \
    asm("mov.b64 {%0, %1}, %2;" : "=f"(lo), "=f"(hi) : "l"(v))

// pack two f32 -> f16x2, tanh both halves in ONE MUFU op
__device__ __forceinline__ uint32_t tanh2_f16(float lo, float hi) {
    uint32_t h;
    asm("cvt.rn.f16x2.f32 %0, %1, %2;" : "=r"(h) : "f"(hi), "f"(lo));
    asm("tanh.approx.f16x2 %0, %0;" : "+r"(h));
    return h;
}
__device__ __forceinline__ void unpack_h2(float& lo, float& hi, uint32_t h) {
    asm("{ .reg .f16 l, u; mov.b32 {l, u}, %2;"
        " cvt.f32.f16 %0, l; cvt.f32.f16 %1, u; }"
        : "=f"(lo), "=f"(hi) : "r"(h));
}
__device__ __forceinline__ float rcp_fast(float x) {
    float y; asm("rcp.approx.f32 %0, %1;" : "=f"(y) : "f"(x)); return y;
}
__device__ __forceinline__ float sqrt_fast(float x) {
    float y; asm("sqrt.approx.f32 %0, %1;" : "=f"(y) : "f"(x)); return y;
}

// ---------------------------------------------------------------------------
// 32-row CTA working set (~53 KB -> 2 CTAs/SM).
// X transposed [k][row] pitch 32; H1h [row][kk] pitch 33 (f16x2 col pairs);
// Part [plane = wq*8+j][row] pitch 34.
// ---------------------------------------------------------------------------
struct __align__(16) Smem {
    float    X[52 * 32];     // MLP input, transposed [k][row]
    uint32_t H1h[32 * 33];   // hidden1 f16x2 col pairs, [row][kk]
    float    Part[32 * 34];  // L3 partials, [plane][row]
    float    W1[50 * 64];    // [k][j]
    float    W2[64 * 64];    // [k][j]
    float    W3d[64 * 16];   // W3 duplicated pairs
    float    Q[32 * 33];     // ypseq circular queue per row
};

// ---------------------------------------------------------------------------
// Grey-box CSTR+flash RHS (scaled); approx rcp/sqrt/exp.
// ---------------------------------------------------------------------------
__device__ __forceinline__ void fg_eval(const float* x, float u0f, float u1f,
                                        float* g) {
    const float Hr  = 0.3f * x[0] + 0.7f;
    const float CAr = 0.2f * x[1] + 0.5f;
    const float CBr = 0.2f * x[2] + 0.5f;
    const float Tr  = 5.0f * x[3] + 310.0f;
    const float Hb  = 0.3f * x[4] + 0.7f;
    const float CAb = 0.2f * x[5] + 0.5f;
    const float CBb = 0.2f * x[6] + 0.5f;
    const float Tb  = 5.0f * x[7] + 310.0f;
    const float Fu  = 0.1f  * u0f + 1.0f;
    const float Du  = 0.05f * u1f + 0.5f;

    const float rden = rcp_fast(3.5f * CAb + 1.1f * CBb);
    const float CAd = 3.5f * CAb * rden;
    const float CBd = 1.1f * CBb * rden;
    const float Fr  = sqrt_fast(Hr);
    const float Fb  = sqrt_fast(Hb);
    const float k1c = 20000.0f * __expf(-3000.0f * rcp_fast(Tr));
    const float r1  = k1c * CAr;
    const float rHr = rcp_fast(Hr);
    const float rHb = rcp_fast(Hb);

    g[0] = (Fu + Du - Fr) * (1.0f / 0.3f);
    g[1] = ((Fu * (1.0f - CAr) + Du * (CAd - CAr)) * rHr - r1) * (1.0f / 0.2f);
    g[2] = ((-Fu * CBr + Du * (CBd - CBr)) * rHr + r1) * (1.0f / 0.2f);
    g[3] = ((Fu * (320.0f - Tr) + Du * (310.0f - Tr)) * rHr
            - (200.0f / 15.0f) * rHr + r1 * (10.0f / 15.0f)) * (1.0f / 5.0f);
    g[4] = (Fr - Fb - Du) * (1.0f / 0.3f);
    g[5] = ((Fr * (CAr - CAb) + Du * (CAb - CAd)) * rHb) * (1.0f / 0.2f);
    g[6] = ((Fr * (CBr - CBb) + Du * (CBb - CBd)) * rHb) * (1.0f / 0.2f);
    g[7] = (Fr * (Tr - Tb) * rHb + (200.0f / 15.0f) * rHb) * (1.0f / 5.0f);
}

// ---------------------------------------------------------------------------
// Persistent kernel: CTA = 32 rows, 128 threads (4 warps), 2 CTAs/SM.
// Warp wq: cols [wq*16, wq*16+16); thread = 1 row (lam) x 16 cols.
// dense1 -> bar -> dense2(+tanh, regs) + fused L3 partials -> bar ->
// owner (lam<8) reduce + fg + RK4 + X rebuild -> bar.
// ---------------------------------------------------------------------------
__global__ void __launch_bounds__(NT, 2)
cstr_flash_kernel(const float* __restrict__ useq, const float* __restrict__ xGz0,
                  const float* __restrict__ gW1, const float* __restrict__ gb1,
                  const float* __restrict__ gW2, const float* __restrict__ gb2,
                  const float* __restrict__ gW3, const float* __restrict__ gb3,
                  float* __restrict__ out, int T) {
    extern __shared__ char smem_raw[];
    Smem& S = *reinterpret_cast<Smem*>(smem_raw);

    const int tid = threadIdx.x;
    const int wq  = tid >> 5;
    const int lam = tid & 31;
    const int j0  = wq * 16;

    // weights
    for (int i = tid; i < 50 * 64; i += NT) S.W1[i] = gW1[i];
    for (int i = tid; i < 64 * 64; i += NT) S.W2[i] = gW2[i];
    for (int i = tid; i < 64 * 8; i += NT) {
        const float w = gW3[i];
        S.W3d[2 * i] = w; S.W3d[2 * i + 1] = w;
    }

    // bias pairs for this warp's 16 columns
    ull bb1[8], bb2[8];
#pragma unroll
    for (int p = 0; p < 8; p++) {
        PACK2(bb1[p], gb1[j0 + 2 * p], gb1[j0 + 2 * p + 1]);
        PACK2(bb2[p], gb2[j0 + 2 * p], gb2[j0 + 2 * p + 1]);
    }

    // owner mapping: lanes 0..7 of each warp own rows wq*8 + lam
    const bool own  = (lam < 8);
    const int  rown = wq * 8 + (lam & 7);
    const long gr   = (long)blockIdx.x * BC + rown;
    float* qrow = S.Q + rown * 33;

    float xG[8], xcur[8], kacc[8], up[8], b3r[8];
    float u0 = 0.f, u1 = 0.f;
#pragma unroll
    for (int c = 0; c < 8; c++) { xG[c] = 0.f; xcur[c] = 0.f; kacc[c] = 0.f; up[c] = 0.f; b3r[c] = 0.f; }

    if (own) {
        const float* x0 = xGz0 + gr * 48;
#pragma unroll
        for (int c = 0; c < 8; c++) xG[c] = x0[c];
#pragma unroll
        for (int m = 0; m < 4; m++)
#pragma unroll
            for (int c = 0; c < 8; c++) qrow[m * 8 + c] = x0[8 + 8 * m + c];
#pragma unroll
        for (int q = 0; q < 8; q++) up[q] = x0[40 + q];
#pragma unroll
        for (int c = 0; c < 8; c++) b3r[c] = gb3[c];
        // initial X (transposed, pitch 32)
#pragma unroll
        for (int c = 0; c < 8; c++)  S.X[c * 32 + rown] = x0[c];
#pragma unroll
        for (int j = 0; j < 32; j++) S.X[(8 + j) * 32 + rown] = x0[8 + j];
#pragma unroll
        for (int q = 0; q < 8; q++)  S.X[(40 + q) * 32 + rown] = x0[40 + q];
        u0 = useq[gr * T * 2 + 0];
        u1 = useq[gr * T * 2 + 1];
        S.X[48 * 32 + rown] = u0;
        S.X[49 * 32 + rown] = u1;
    }
    __syncthreads();

#pragma unroll 1
    for (int t = 0; t < T; t++) {
        if (own) {   // y_t = xG (pre-update)
            float* op = out + (gr * T + t) * 8;
            *(float4*)(op)     = make_float4(xG[0], xG[1], xG[2], xG[3]);
            *(float4*)(op + 4) = make_float4(xG[4], xG[5], xG[6], xG[7]);
        }

#pragma unroll 1
        for (int s = 0; s < 4; s++) {
            // ---- dense1: X (f32) -> H1h (f16x2 col pairs) ----
            {
                ull a[8];
#pragma unroll
                for (int p = 0; p < 8; p++) a[p] = bb1[p];
                const float* xs = S.X + lam;
                const float* wj = S.W1 + j0;
#pragma unroll 10
                for (int k = 0; k < 50; k++) {
                    const float xv = xs[k * 32];
                    ull xa;
                    PACK2(xa, xv, xv);
                    const float* w = wj + k * 64;
                    const ulonglong2 wA = *(const ulonglong2*)(w);
                    const ulonglong2 wB = *(const ulonglong2*)(w + 4);
                    const ulonglong2 wC = *(const ulonglong2*)(w + 8);
                    const ulonglong2 wD = *(const ulonglong2*)(w + 12);
                    FMA2(a[0], xa, wA.x, a[0]);
                    FMA2(a[1], xa, wA.y, a[1]);
                    FMA2(a[2], xa, wB.x, a[2]);
                    FMA2(a[3], xa, wB.y, a[3]);
                    FMA2(a[4], xa, wC.x, a[4]);
                    FMA2(a[5], xa, wC.y, a[5]);
                    FMA2(a[6], xa, wD.x, a[6]);
                    FMA2(a[7], xa, wD.y, a[7]);
                }
#pragma unroll
                for (int q = 0; q < 8; q++) {
                    float f0, f1;
                    UNPACK2(f0, f1, a[q]);
                    S.H1h[lam * 33 + wq * 8 + q] = tanh2_f16(f0, f1);
                }
            }
            __syncthreads();

            // ---- dense2 (H1h -> regs) ----
            ull a[8];
#pragma unroll
            for (int p = 0; p < 8; p++) a[p] = bb2[p];
            {
                const uint32_t* xs = S.H1h + lam * 33;
                const float* wj = S.W2 + j0;
#pragma unroll 8
                for (int kk = 0; kk < 32; kk++) {
                    float x0f, x1f;
                    unpack_h2(x0f, x1f, xs[kk]);
                    ull xa, xb;
                    PACK2(xa, x0f, x0f);
                    PACK2(xb, x1f, x1f);
                    const float* w0 = wj + (2 * kk) * 64;
                    const float* w1 = wj + (2 * kk + 1) * 64;
                    const ulonglong2 wA0 = *(const ulonglong2*)(w0);
                    const ulonglong2 wB0 = *(const ulonglong2*)(w0 + 4);
                    const ulonglong2 wC0 = *(const ulonglong2*)(w0 + 8);
                    const ulonglong2 wD0 = *(const ulonglong2*)(w0 + 12);
                    FMA2(a[0], xa, wA0.x, a[0]);
                    FMA2(a[1], xa, wA0.y, a[1]);
                    FMA2(a[2], xa, wB0.x, a[2]);
                    FMA2(a[3], xa, wB0.y, a[3]);
                    FMA2(a[4], xa, wC0.x, a[4]);
                    FMA2(a[5], xa, wC0.y, a[5]);
                    FMA2(a[6], xa, wD0.x, a[6]);
                    FMA2(a[7], xa, wD0.y, a[7]);
                    const ulonglong2 wA1 = *(const ulonglong2*)(w1);
                    const ulonglong2 wB1 = *(const ulonglong2*)(w1 + 4);
                    const ulonglong2 wC1 = *(const ulonglong2*)(w1 + 8);
                    const ulonglong2 wD1 = *(const ulonglong2*)(w1 + 12);
                    FMA2(a[0], xb, wA1.x, a[0]);
                    FMA2(a[1], xb, wA1.y, a[1]);
                    FMA2(a[2], xb, wB1.x, a[2]);
                    FMA2(a[3], xb, wB1.y, a[3]);
                    FMA2(a[4], xb, wC1.x, a[4]);
                    FMA2(a[5], xb, wC1.y, a[5]);
                    FMA2(a[6], xb, wD1.x, a[6]);
                    FMA2(a[7], xb, wD1.y, a[7]);
                }
            }
            // tanh -> 16 H2 values (this row, cols j0..j0+15)
            float th[16];
#pragma unroll
            for (int q = 0; q < 8; q++) {
                float f0, f1;
                UNPACK2(f0, f1, a[q]);
                unpack_h2(th[2 * q], th[2 * q + 1], tanh2_f16(f0, f1));
            }

            // ---- fused L3 partials: p3[q] = {P_j=2q, P_j=2q+1} for this row ----
            ull p3[4];
            p3[0] = 0ull; p3[1] = 0ull; p3[2] = 0ull; p3[3] = 0ull;
#pragma unroll
            for (int i = 0; i < 16; i++) {
                ull xp;
                PACK2(xp, th[i], th[i]);
                const ull* wd = (const ull*)(S.W3d) + (j0 + i) * 8;
                const ulonglong2 w0 = *(const ulonglong2*)(wd);
                const ulonglong2 w1 = *(const ulonglong2*)(wd + 2);
                // w0.x = {w[i][0],w[i][0]}? no: W3d holds dup pairs {w,w} per j.
                // (const ull*)W3d + (j0+i)*8 indexes 8 ull = 8 j-dup pairs.
                FMA2(p3[0], xp, w0.x, p3[0]);
                FMA2(p3[1], xp, w0.y, p3[1]);
                FMA2(p3[2], xp, w1.x, p3[2]);
                FMA2(p3[3], xp, w1.y, p3[3]);
                const ulonglong2 w2 = *(const ulonglong2*)(wd + 4);
                const ulonglong2 w3 = *(const ulonglong2*)(wd + 6);
                // p3 pairs hold (j,j+1): use dup-x against per-j dup weights:
                // actually each wd ull = {w_j, w_j} dup; FMA2(xp={t,t}, w={w,w})
                // accumulates the same product twice -> we only need 4 ull for
                // 8 j outputs if weights are packed {w_j, w_j+1}. Repack below.
                (void)w2; (void)w3;
            }
            // NOTE: the loop above is replaced by the correct packing below.
            p3[0] = 0ull; p3[1] = 0ull; p3[2] = 0ull; p3[3] = 0ull;
#pragma unroll
            for (int i = 0; i < 16; i++) {
                ull xp;
                PACK2(xp, th[i], th[i]);
                // W3 row (j0+i): consecutive j values w[0..7] live at
                // S.W3d[(j0+i)*16 + 2*j] duplicated; the PAIRED view
                // {w_j, w_j+1} is simply the original W3 row: use gsrc below.
                const float* wrow = S.W3d + (j0 + i) * 16;
                // build {w0,w1},{w2,w3},{w4,w5},{w6,w7} from dup storage:
                // dup storage: [w0,w0,w1,w1,...]; elements 0,2,4,...
                ull wp0, wp1, wp2, wp3;
                PACK2(wp0, wrow[0],  wrow[2]);
                PACK2(wp1, wrow[4],  wrow[6]);
                PACK2(wp2, wrow[8],  wrow[10]);
                PACK2(wp3, wrow[12], wrow[14]);
                FMA2(p3[0], xp, wp0, p3[0]);
                FMA2(p3[1], xp, wp1, p3[1]);
                FMA2(p3[2], xp, wp2, p3[2]);
                FMA2(p3[3], xp, wp3, p3[3]);
            }
            // store partials: plane (wq*8 + j), row lam
#pragma unroll
            for (int q = 0; q < 4; q++) {
                float pa, pb;
                UNPACK2(pa, pb, p3[q]);
                S.Part[(wq * 8 + 2 * q) * 34 + lam]     = pa;
                S.Part[(wq * 8 + 2 * q + 1) * 34 + lam] = pb;
            }
            __syncthreads();

            // ---- owner: reduce partials + fg + RK4 + X rebuild ----
            if (own) {
                float fnn[8];
#pragma unroll
                for (int j = 0; j < 8; j++) fnn[j] = b3r[j];
#pragma unroll
                for (int w = 0; w < 4; w++)
#pragma unroll
                    for (int j = 0; j < 8; j++)
                        fnn[j] += S.Part[(w * 8 + j) * 34 + rown];

                float g[8];
                fg_eval((s == 0) ? xG : xcur, u0, u1, g);
                float kv[8];
#pragma unroll
                for (int c = 0; c < 8; c++) kv[c] = g[c] + fnn[c];

                if (s == 0) {
#pragma unroll
                    for (int c = 0; c < 8; c++) {
                        kacc[c] = kv[c];
                        xcur[c] = xG[c] + 0.005f * kv[c];
                    }
#pragma unroll
                    for (int m = 0; m < 4; m++) {
                        const float* qa = qrow + ((t + m) & 3) * 8;
                        const float* qb = qrow + ((t + m + 1) & 3) * 8;
#pragma unroll
                        for (int c = 0; c < 8; c++) {
                            const float nb = (m < 3) ? qb[c] : xG[c];
                            S.X[(8 + m * 8 + c) * 32 + rown] = 0.5f * (qa[c] + nb);
                        }
                    }
                } else if (s == 1) {
#pragma unroll
                    for (int c = 0; c < 8; c++) {
                        kacc[c] += 2.0f * kv[c];
                        xcur[c] = xG[c] + 0.005f * kv[c];
                    }
                } else if (s == 2) {
#pragma unroll
                    for (int c = 0; c < 8; c++) {
                        kacc[c] += 2.0f * kv[c];
                        xcur[c] = xG[c] + 0.01f * kv[c];
                    }
#pragma unroll
                    for (int m = 0; m < 4; m++) {
                        const float* qb = qrow + ((t + m + 1) & 3) * 8;
#pragma unroll
                        for (int c = 0; c < 8; c++) {
                            const float z = (m < 3) ? qb[c] : xG[c];
                            S.X[(8 + m * 8 + c) * 32 + rown] = z;
                        }
                    }
                } else {
#pragma unroll
                    for (int c = 0; c < 8; c++) kacc[c] += kv[c];
                    float xnew[8];
#pragma unroll
                    for (int c = 0; c < 8; c++)
                        xnew[c] = xG[c] + (0.01f / 6.0f) * kacc[c];
                    {
                        float* qo = qrow + (t & 3) * 8;
#pragma unroll
                        for (int c = 0; c < 8; c++) qo[c] = xG[c];
                    }
#pragma unroll
                    for (int m = 0; m < 4; m++) {
                        const float* qn = qrow + ((t + 1 + m) & 3) * 8;
#pragma unroll
                        for (int c = 0; c < 8; c++)
                            S.X[(8 + m * 8 + c) * 32 + rown] = qn[c];
                    }
#pragma unroll
                    for (int q = 0; q < 6; q++) up[q] = up[q + 2];
                    up[6] = u0; up[7] = u1;
#pragma unroll
                    for (int q = 0; q < 8; q++)
                        S.X[(40 + q) * 32 + rown] = up[q];
                    if (t + 1 < T) {
                        u0 = useq[(gr * T + t + 1) * 2 + 0];
                        u1 = useq[(gr * T + t + 1) * 2 + 1];
                    }
                    S.X[48 * 32 + rown] = u0;
                    S.X[49 * 32 + rown] = u1;
#pragma unroll
                    for (int c = 0; c < 8; c++) xG[c] = xnew[c];
                }
                const float* xw = (s == 3) ? xG : xcur;
#pragma unroll
                for (int c = 0; c < 8; c++)
                    S.X[c * 32 + rown] = xw[c];
            }
            __syncthreads();
        }
    }
}

// ---------------------------------------------------------------------------
extern "C" void kernel_launch(void* const* d_in, const int* in_sizes, int n_in,
                              void* d_out, int out_size) {
    const float* useq = (const float*)d_in[0];
    const float* xGz0 = (const float*)d_in[1];
    const float* W1   = (const float*)d_in[2];
    const float* b1   = (const float*)d_in[3];
    const float* W2   = (const float*)d_in[4];
    const float* b2   = (const float*)d_in[5];
    const float* W3   = (const float*)d_in[6];
    const float* b3   = (const float*)d_in[7];
    float* out = (float*)d_out;

    const int B = in_sizes[1] / 48;
    const int T = in_sizes[0] / (B * 2);

    const int smem = (int)sizeof(Smem);
    cudaFuncSetAttribute(cstr_flash_kernel,
                         cudaFuncAttributeMaxDynamicSharedMemorySize, smem);
    cstr_flash_kernel<<<B / BC, NT, smem>>>(useq, xGz0, W1, b1, W2, b2, W3, b3,
                                            out, T);
}

// round 15
// speedup vs baseline: 1.4303x; 1.4303x over previous
#include <cuda_runtime.h>
#include <cuda_fp16.h>
#include <math.h>
#include <cstdint>

#define NT 256
#define BC 64
typedef unsigned long long ull;

#define FMA2(d, a, b, c) \
    asm("fma.rn.f32x2 %0, %1, %2, %3;" : "=l"(d) : "l"(a), "l"(b), "l"(c))
#define PACK2(d, lo, hi) \
    asm("mov.b64 %0, {%1, %2};" : "=l"(d) : "f"(lo), "f"(hi))
#define UNPACK2(lo, hi, v) \
    asm("mov.b64 {%0, %1}, %2;" : "=f"(lo), "=f"(hi) : "l"(v))
#define HFMA2(d, a, b, c) \
    asm("fma.rn.f16x2 %0, %1, %2, %3;" : "=r"(d) : "r"(a), "r"(b), "r"(c))
#define PRMT(d, a, b, sel) \
    asm("prmt.b32 %0, %1, %2, %3;" : "=r"(d) : "r"(a), "r"(b), "n"(sel))

__device__ __forceinline__ uint32_t tanh2h(uint32_t h) {
    asm("tanh.approx.f16x2 %0, %0;" : "+r"(h));
    return h;
}
// f16x2 -> two f32
__device__ __forceinline__ void unpack_h2(float& lo, float& hi, uint32_t h) {
    asm("{ .reg .f16 l, u; mov.b32 {l, u}, %2;"
        " cvt.f32.f16 %0, l; cvt.f32.f16 %1, u; }"
        : "=f"(lo), "=f"(hi) : "r"(h));
}
// two f32 -> f16x2 (lo in low half)
__device__ __forceinline__ uint32_t pack_h2(float lo, float hi) {
    uint32_t h;
    asm("cvt.rn.f16x2.f32 %0, %1, %2;" : "=r"(h) : "f"(hi), "f"(lo));
    return h;
}
__device__ __forceinline__ float rcp_fast(float x) {
    float y; asm("rcp.approx.f32 %0, %1;" : "=f"(y) : "f"(x)); return y;
}
__device__ __forceinline__ float sqrt_fast(float x) {
    float y; asm("sqrt.approx.f32 %0, %1;" : "=f"(y) : "f"(x)); return y;
}

// ---------------------------------------------------------------------------
// f32 arrays first (16B alignment), then f16 arrays (sizes mult of 8 halves).
// Xh/H1h: [k][row] halves, 64 halves (128B) per k-row -> conflict-free.
// ---------------------------------------------------------------------------
struct __align__(16) Smem {
    float  Part[64 * 66];   // L3 partials: plane (w*8+j), float index = row
    float  W3d[64 * 16];    // W3 duplicated pairs {w,w} per j
    float  Q[64 * 33];      // ypseq circular queue per row (f32)
    __half Xh[52 * 64];     // MLP input, [k][row] f16
    __half W1h[50 * 64];    // [k][j] f16
    __half W2h[64 * 64];    // [k][j] f16
    __half H1h[64 * 64];    // hidden1, [j][row] f16
};

// ---------------------------------------------------------------------------
// Grey-box CSTR+flash RHS (scaled); approx rcp/sqrt/exp.
// ---------------------------------------------------------------------------
__device__ __forceinline__ void fg_eval(const float* x, float u0f, float u1f,
                                        float* g) {
    const float Hr  = 0.3f * x[0] + 0.7f;
    const float CAr = 0.2f * x[1] + 0.5f;
    const float CBr = 0.2f * x[2] + 0.5f;
    const float Tr  = 5.0f * x[3] + 310.0f;
    const float Hb  = 0.3f * x[4] + 0.7f;
    const float CAb = 0.2f * x[5] + 0.5f;
    const float CBb = 0.2f * x[6] + 0.5f;
    const float Tb  = 5.0f * x[7] + 310.0f;
    const float Fu  = 0.1f  * u0f + 1.0f;
    const float Du  = 0.05f * u1f + 0.5f;

    const float rden = rcp_fast(3.5f * CAb + 1.1f * CBb);
    const float CAd = 3.5f * CAb * rden;
    const float CBd = 1.1f * CBb * rden;
    const float Fr  = sqrt_fast(Hr);
    const float Fb  = sqrt_fast(Hb);
    const float k1c = 20000.0f * __expf(-3000.0f * rcp_fast(Tr));
    const float r1  = k1c * CAr;
    const float rHr = rcp_fast(Hr);
    const float rHb = rcp_fast(Hb);

    g[0] = (Fu + Du - Fr) * (1.0f / 0.3f);
    g[1] = ((Fu * (1.0f - CAr) + Du * (CAd - CAr)) * rHr - r1) * (1.0f / 0.2f);
    g[2] = ((-Fu * CBr + Du * (CBd - CBr)) * rHr + r1) * (1.0f / 0.2f);
    g[3] = ((Fu * (320.0f - Tr) + Du * (310.0f - Tr)) * rHr
            - (200.0f / 15.0f) * rHr + r1 * (10.0f / 15.0f)) * (1.0f / 5.0f);
    g[4] = (Fr - Fb - Du) * (1.0f / 0.3f);
    g[5] = ((Fr * (CAr - CAb) + Du * (CAb - CAd)) * rHb) * (1.0f / 0.2f);
    g[6] = ((Fr * (CBr - CBb) + Du * (CBb - CBd)) * rHb) * (1.0f / 0.2f);
    g[7] = (Fr * (Tr - Tb) * rHb + (200.0f / 15.0f) * rHb) * (1.0f / 5.0f);
}

// ---------------------------------------------------------------------------
// Persistent kernel: CTA = 64 rows, 256 threads (8 warps, 2/SMSP), grid 128.
// Warp wid: cols [wid*8, wid*8+8); thread = rows {2lam, 2lam+1} x 8 cols.
// dense1 (HFMA2) -> bar -> dense2 (HFMA2) + fused L3 (f32) -> bar ->
// owner reduce + fg + RK4 + X rebuild -> bar.
// ---------------------------------------------------------------------------
__global__ void __launch_bounds__(NT, 1)
cstr_flash_kernel(const float* __restrict__ useq, const float* __restrict__ xGz0,
                  const float* __restrict__ gW1, const float* __restrict__ gb1,
                  const float* __restrict__ gW2, const float* __restrict__ gb2,
                  const float* __restrict__ gW3, const float* __restrict__ gb3,
                  float* __restrict__ out, int T) {
    extern __shared__ char smem_raw[];
    Smem& S = *reinterpret_cast<Smem*>(smem_raw);

    const int tid = threadIdx.x;
    const int wid = tid >> 5;
    const int lam = tid & 31;
    const int j0  = wid * 8;

    // weights (f16) + W3 dup (f32)
    for (int i = tid; i < 50 * 64; i += NT) S.W1h[i] = __float2half(gW1[i]);
    for (int i = tid; i < 64 * 64; i += NT) S.W2h[i] = __float2half(gW2[i]);
    for (int i = tid; i < 64 * 8; i += NT) {
        const float w = gW3[i];
        S.W3d[2 * i] = w; S.W3d[2 * i + 1] = w;
    }

    // bias col-pairs (f16x2) for this warp's 8 columns
    uint32_t bb1h[4], bb2h[4];
#pragma unroll
    for (int p = 0; p < 4; p++) {
        bb1h[p] = pack_h2(gb1[j0 + 2 * p], gb1[j0 + 2 * p + 1]);
        bb2h[p] = pack_h2(gb2[j0 + 2 * p], gb2[j0 + 2 * p + 1]);
    }

    // owner mapping: lanes 0..7 of each warp own rows wid*8 + lam
    const bool own  = (lam < 8);
    const int  rown = wid * 8 + (lam & 7);
    const long gr   = (long)blockIdx.x * BC + rown;
    float* qrow = S.Q + rown * 33;

    float xG[8], xcur[8], kacc[8], up[8], b3r[8];
    float u0 = 0.f, u1 = 0.f;
#pragma unroll
    for (int c = 0; c < 8; c++) { xG[c] = 0.f; xcur[c] = 0.f; kacc[c] = 0.f; up[c] = 0.f; b3r[c] = 0.f; }

    if (own) {
        const float* x0 = xGz0 + gr * 48;
#pragma unroll
        for (int c = 0; c < 8; c++) xG[c] = x0[c];
#pragma unroll
        for (int m = 0; m < 4; m++)
#pragma unroll
            for (int c = 0; c < 8; c++) qrow[m * 8 + c] = x0[8 + 8 * m + c];
#pragma unroll
        for (int q = 0; q < 8; q++) up[q] = x0[40 + q];
#pragma unroll
        for (int c = 0; c < 8; c++) b3r[c] = gb3[c];
        // initial X (f16, [k][row])
#pragma unroll
        for (int k = 0; k < 48; k++) S.Xh[k * 64 + rown] = __float2half(x0[k]);
        u0 = useq[gr * T * 2 + 0];
        u1 = useq[gr * T * 2 + 1];
        S.Xh[48 * 64 + rown] = __float2half(u0);
        S.Xh[49 * 64 + rown] = __float2half(u1);
        S.Xh[50 * 64 + rown] = __half(0.0f);
        S.Xh[51 * 64 + rown] = __half(0.0f);
    }
    __syncthreads();

#pragma unroll 1
    for (int t = 0; t < T; t++) {
        if (own) {   // y_t = xG (pre-update)
            float* op = out + (gr * T + t) * 8;
            *(float4*)(op)     = make_float4(xG[0], xG[1], xG[2], xG[3]);
            *(float4*)(op + 4) = make_float4(xG[4], xG[5], xG[6], xG[7]);
        }

#pragma unroll 1
        for (int s = 0; s < 4; s++) {
            // ---- dense1 (HFMA2): Xh -> H1h ----
            {
                uint32_t a0[4], a1[4];
#pragma unroll
                for (int p = 0; p < 4; p++) { a0[p] = bb1h[p]; a1[p] = bb1h[p]; }
                const uint32_t* xs = (const uint32_t*)(S.Xh) + lam;
                const __half* wj = S.W1h + j0;
#pragma unroll 10
                for (int k = 0; k < 50; k++) {
                    const uint32_t xp = xs[k * 32];         // {r0, r1}
                    uint32_t xa, xb;
                    PRMT(xa, xp, xp, 0x1010);               // {r0, r0}
                    PRMT(xb, xp, xp, 0x3232);               // {r1, r1}
                    const uint4 wv = *(const uint4*)(wj + k * 64);
                    HFMA2(a0[0], xa, wv.x, a0[0]);  HFMA2(a1[0], xb, wv.x, a1[0]);
                    HFMA2(a0[1], xa, wv.y, a0[1]);  HFMA2(a1[1], xb, wv.y, a1[1]);
                    HFMA2(a0[2], xa, wv.z, a0[2]);  HFMA2(a1[2], xb, wv.z, a1[2]);
                    HFMA2(a0[3], xa, wv.w, a0[3]);  HFMA2(a1[3], xb, wv.w, a1[3]);
                }
                // tanh on f16x2 accs, transpose col-pairs -> row-pairs, store
                uint32_t* hs = (uint32_t*)(S.H1h) + lam;
#pragma unroll
                for (int p = 0; p < 4; p++) {
                    const uint32_t t0 = tanh2h(a0[p]);      // row0: {j2p, j2p+1}
                    const uint32_t t1 = tanh2h(a1[p]);      // row1
                    uint32_t lo, hi;
                    PRMT(lo, t0, t1, 0x5410);               // {r0 j2p,   r1 j2p}
                    PRMT(hi, t0, t1, 0x7632);               // {r0 j2p+1, r1 j2p+1}
                    hs[(j0 + 2 * p) * 32]     = lo;
                    hs[(j0 + 2 * p + 1) * 32] = hi;
                }
            }
            __syncthreads();

            // ---- dense2 (HFMA2): H1h -> regs ----
            uint32_t a0[4], a1[4];
#pragma unroll
            for (int p = 0; p < 4; p++) { a0[p] = bb2h[p]; a1[p] = bb2h[p]; }
            {
                const uint32_t* xs = (const uint32_t*)(S.H1h) + lam;
                const __half* wj = S.W2h + j0;
#pragma unroll 8
                for (int k = 0; k < 64; k++) {
                    const uint32_t xp = xs[k * 32];
                    uint32_t xa, xb;
                    PRMT(xa, xp, xp, 0x1010);
                    PRMT(xb, xp, xp, 0x3232);
                    const uint4 wv = *(const uint4*)(wj + k * 64);
                    HFMA2(a0[0], xa, wv.x, a0[0]);  HFMA2(a1[0], xb, wv.x, a1[0]);
                    HFMA2(a0[1], xa, wv.y, a0[1]);  HFMA2(a1[1], xb, wv.y, a1[1]);
                    HFMA2(a0[2], xa, wv.z, a0[2]);  HFMA2(a1[2], xb, wv.z, a1[2]);
                    HFMA2(a0[3], xa, wv.w, a0[3]);  HFMA2(a1[3], xb, wv.w, a1[3]);
                }
            }
            // tanh -> f32 row pairs for fused L3
            ull h2p[8];
#pragma unroll
            for (int p = 0; p < 4; p++) {
                const uint32_t t0 = tanh2h(a0[p]);   // row0: {j2p, j2p+1}
                const uint32_t t1 = tanh2h(a1[p]);   // row1
                float f00, f01, f10, f11;
                unpack_h2(f00, f01, t0);
                unpack_h2(f10, f11, t1);
                PACK2(h2p[2 * p],     f00, f10);     // col j2p:   {r0, r1}
                PACK2(h2p[2 * p + 1], f01, f11);     // col j2p+1
            }

            // ---- fused L3 partials (f32): p3[j] = {P_r0[j], P_r1[j]} ----
            ull p3[8];
#pragma unroll
            for (int j = 0; j < 8; j++) p3[j] = 0ull;
#pragma unroll
            for (int i = 0; i < 8; i++) {
                const ull xp = h2p[i];
                const ull* wd = (const ull*)(S.W3d) + (j0 + i) * 8;
                const ulonglong2 w0 = *(const ulonglong2*)(wd);
                const ulonglong2 w1 = *(const ulonglong2*)(wd + 2);
                const ulonglong2 w2 = *(const ulonglong2*)(wd + 4);
                const ulonglong2 w3 = *(const ulonglong2*)(wd + 6);
                FMA2(p3[0], xp, w0.x, p3[0]);
                FMA2(p3[1], xp, w0.y, p3[1]);
                FMA2(p3[2], xp, w1.x, p3[2]);
                FMA2(p3[3], xp, w1.y, p3[3]);
                FMA2(p3[4], xp, w2.x, p3[4]);
                FMA2(p3[5], xp, w2.y, p3[5]);
                FMA2(p3[6], xp, w3.x, p3[6]);
                FMA2(p3[7], xp, w3.y, p3[7]);
            }
#pragma unroll
            for (int j = 0; j < 8; j++)
                *(ull*)(S.Part + (wid * 8 + j) * 66 + 2 * lam) = p3[j];
            __syncthreads();

            // ---- owner: reduce partials + fg + RK4 + X rebuild ----
            if (own) {
                float fnn[8];
#pragma unroll
                for (int j = 0; j < 8; j++) fnn[j] = b3r[j];
#pragma unroll
                for (int w = 0; w < 8; w++)
#pragma unroll
                    for (int j = 0; j < 8; j++)
                        fnn[j] += S.Part[(w * 8 + j) * 66 + rown];

                float g[8];
                fg_eval((s == 0) ? xG : xcur, u0, u1, g);
                float kv[8];
#pragma unroll
                for (int c = 0; c < 8; c++) kv[c] = g[c] + fnn[c];

                if (s == 0) {
#pragma unroll
                    for (int c = 0; c < 8; c++) {
                        kacc[c] = kv[c];
                        xcur[c] = xG[c] + 0.005f * kv[c];
                    }
#pragma unroll
                    for (int m = 0; m < 4; m++) {
                        const float* qa = qrow + ((t + m) & 3) * 8;
                        const float* qb = qrow + ((t + m + 1) & 3) * 8;
#pragma unroll
                        for (int c = 0; c < 8; c++) {
                            const float nb = (m < 3) ? qb[c] : xG[c];
                            S.Xh[(8 + m * 8 + c) * 64 + rown] =
                                __float2half(0.5f * (qa[c] + nb));
                        }
                    }
                } else if (s == 1) {
#pragma unroll
                    for (int c = 0; c < 8; c++) {
                        kacc[c] += 2.0f * kv[c];
                        xcur[c] = xG[c] + 0.005f * kv[c];
                    }
                } else if (s == 2) {
#pragma unroll
                    for (int c = 0; c < 8; c++) {
                        kacc[c] += 2.0f * kv[c];
                        xcur[c] = xG[c] + 0.01f * kv[c];
                    }
#pragma unroll
                    for (int m = 0; m < 4; m++) {
                        const float* qb = qrow + ((t + m + 1) & 3) * 8;
#pragma unroll
                        for (int c = 0; c < 8; c++) {
                            const float z = (m < 3) ? qb[c] : xG[c];
                            S.Xh[(8 + m * 8 + c) * 64 + rown] = __float2half(z);
                        }
                    }
                } else {
#pragma unroll
                    for (int c = 0; c < 8; c++) kacc[c] += kv[c];
                    float xnew[8];
#pragma unroll
                    for (int c = 0; c < 8; c++)
                        xnew[c] = xG[c] + (0.01f / 6.0f) * kacc[c];
                    {
                        float* qo = qrow + (t & 3) * 8;
#pragma unroll
                        for (int c = 0; c < 8; c++) qo[c] = xG[c];
                    }
#pragma unroll
                    for (int m = 0; m < 4; m++) {
                        const float* qn = qrow + ((t + 1 + m) & 3) * 8;
#pragma unroll
                        for (int c = 0; c < 8; c++)
                            S.Xh[(8 + m * 8 + c) * 64 + rown] =
                                __float2half(qn[c]);
                    }
#pragma unroll
                    for (int q = 0; q < 6; q++) up[q] = up[q + 2];
                    up[6] = u0; up[7] = u1;
#pragma unroll
                    for (int q = 0; q < 8; q++)
                        S.Xh[(40 + q) * 64 + rown] = __float2half(up[q]);
                    if (t + 1 < T) {
                        u0 = useq[(gr * T + t + 1) * 2 + 0];
                        u1 = useq[(gr * T + t + 1) * 2 + 1];
                    }
                    S.Xh[48 * 64 + rown] = __float2half(u0);
                    S.Xh[49 * 64 + rown] = __float2half(u1);
#pragma unroll
                    for (int c = 0; c < 8; c++) xG[c] = xnew[c];
                }
                const float* xw = (s == 3) ? xG : xcur;
#pragma unroll
                for (int c = 0; c < 8; c++)
                    S.Xh[c * 64 + rown] = __float2half(xw[c]);
            }
            __syncthreads();
        }
    }
}

// ---------------------------------------------------------------------------
extern "C" void kernel_launch(void* const* d_in, const int* in_sizes, int n_in,
                              void* d_out, int out_size) {
    const float* useq = (const float*)d_in[0];
    const float* xGz0 = (const float*)d_in[1];
    const float* W1   = (const float*)d_in[2];
    const float* b1   = (const float*)d_in[3];
    const float* W2   = (const float*)d_in[4];
    const float* b2   = (const float*)d_in[5];
    const float* W3   = (const float*)d_in[6];
    const float* b3   = (const float*)d_in[7];
    float* out = (float*)d_out;

    const int B = in_sizes[1] / 48;
    const int T = in_sizes[0] / (B * 2);

    const int smem = (int)sizeof(Smem);
    cudaFuncSetAttribute(cstr_flash_kernel,
                         cudaFuncAttributeMaxDynamicSharedMemorySize, smem);
    cstr_flash_kernel<<<B / BC, NT, smem>>>(useq, xGz0, W1, b1, W2, b2, W3, b3,
                                            out, T);
}

// round 16
// speedup vs baseline: 1.4899x; 1.0416x over previous
#include <cuda_runtime.h>
#include <cuda_fp16.h>
#include <math.h>
#include <cstdint>

#define NT 256
#define BC 64
typedef unsigned long long ull;

#define FMA2(d, a, b, c) \
    asm("fma.rn.f32x2 %0, %1, %2, %3;" : "=l"(d) : "l"(a), "l"(b), "l"(c))
#define PACK2(d, lo, hi) \
    asm("mov.b64 %0, {%1, %2};" : "=l"(d) : "f"(lo), "f"(hi))
#define UNPACK2(lo, hi, v) \
    asm("mov.b64 {%0, %1}, %2;" : "=f"(lo), "=f"(hi) : "l"(v))
#define HFMA2(d, a, b, c) \
    asm("fma.rn.f16x2 %0, %1, %2, %3;" : "=r"(d) : "r"(a), "r"(b), "r"(c))
#define PRMT(d, a, b, sel) \
    asm("prmt.b32 %0, %1, %2, %3;" : "=r"(d) : "r"(a), "r"(b), "n"(sel))

__device__ __forceinline__ uint32_t tanh2h(uint32_t h) {
    asm("tanh.approx.f16x2 %0, %0;" : "+r"(h));
    return h;
}
__device__ __forceinline__ void unpack_h2(float& lo, float& hi, uint32_t h) {
    asm("{ .reg .f16 l, u; mov.b32 {l, u}, %2;"
        " cvt.f32.f16 %0, l; cvt.f32.f16 %1, u; }"
        : "=f"(lo), "=f"(hi) : "r"(h));
}
// two f32 -> f16x2 (lo in low half)
__device__ __forceinline__ uint32_t pack_h2(float lo, float hi) {
    uint32_t h;
    asm("cvt.rn.f16x2.f32 %0, %1, %2;" : "=r"(h) : "f"(hi), "f"(lo));
    return h;
}
__device__ __forceinline__ float rcp_fast(float x) {
    float y; asm("rcp.approx.f32 %0, %1;" : "=f"(y) : "f"(x)); return y;
}
__device__ __forceinline__ float sqrt_fast(float x) {
    float y; asm("sqrt.approx.f32 %0, %1;" : "=f"(y) : "f"(x)); return y;
}

// ---------------------------------------------------------------------------
// Warp-private activation regions; CTA-shared read-only weights.
// Xd: dup f16x2 words [k][row] (pitch 64 u32); Hd: [row][k] dup words, pitch 68.
// ---------------------------------------------------------------------------
struct __align__(16) Smem {
    float    W3[64 * 8];     // f32 [k][j] (ull view gives {j,j+1} pairs)
    float    Q[64 * 33];     // ypseq circular queue per row
    uint32_t Xd[52 * 64];    // MLP input, dup f16x2 {v,v}, [k][row]
    uint32_t Hd[64 * 68];    // hidden1, dup f16x2, [row][k], pitch 68
    __half   W1h[50 * 64];   // f16 [k][j]
    __half   W2h[64 * 64];   // f16 [k][j]
};

// ---------------------------------------------------------------------------
// Grey-box CSTR+flash RHS (scaled); approx rcp/sqrt/exp.
// ---------------------------------------------------------------------------
__device__ __forceinline__ void fg_eval(const float* x, float u0f, float u1f,
                                        float* g) {
    const float Hr  = 0.3f * x[0] + 0.7f;
    const float CAr = 0.2f * x[1] + 0.5f;
    const float CBr = 0.2f * x[2] + 0.5f;
    const float Tr  = 5.0f * x[3] + 310.0f;
    const float Hb  = 0.3f * x[4] + 0.7f;
    const float CAb = 0.2f * x[5] + 0.5f;
    const float CBb = 0.2f * x[6] + 0.5f;
    const float Tb  = 5.0f * x[7] + 310.0f;
    const float Fu  = 0.1f  * u0f + 1.0f;
    const float Du  = 0.05f * u1f + 0.5f;

    const float rden = rcp_fast(3.5f * CAb + 1.1f * CBb);
    const float CAd = 3.5f * CAb * rden;
    const float CBd = 1.1f * CBb * rden;
    const float Fr  = sqrt_fast(Hr);
    const float Fb  = sqrt_fast(Hb);
    const float k1c = 20000.0f * __expf(-3000.0f * rcp_fast(Tr));
    const float r1  = k1c * CAr;
    const float rHr = rcp_fast(Hr);
    const float rHb = rcp_fast(Hb);

    g[0] = (Fu + Du - Fr) * (1.0f / 0.3f);
    g[1] = ((Fu * (1.0f - CAr) + Du * (CAd - CAr)) * rHr - r1) * (1.0f / 0.2f);
    g[2] = ((-Fu * CBr + Du * (CBd - CBr)) * rHr + r1) * (1.0f / 0.2f);
    g[3] = ((Fu * (320.0f - Tr) + Du * (310.0f - Tr)) * rHr
            - (200.0f / 15.0f) * rHr + r1 * (10.0f / 15.0f)) * (1.0f / 5.0f);
    g[4] = (Fr - Fb - Du) * (1.0f / 0.3f);
    g[5] = ((Fr * (CAr - CAb) + Du * (CAb - CAd)) * rHb) * (1.0f / 0.2f);
    g[6] = ((Fr * (CBr - CBb) + Du * (CBb - CBd)) * rHb) * (1.0f / 0.2f);
    g[7] = (Fr * (Tr - Tb) * rHb + (200.0f / 15.0f) * rHb) * (1.0f / 5.0f);
}

// ---------------------------------------------------------------------------
// Persistent kernel: CTA = 64 rows, 256 threads (8 warps, 2/SMSP), grid 128.
// Warp wid owns rows [8*wid, 8*wid+8) END-TO-END. Lane: row = lam&7,
// col group cg = lam>>3 (16 cols each). NO __syncthreads in the main loop.
// ---------------------------------------------------------------------------
__global__ void __launch_bounds__(NT, 1)
cstr_flash_kernel(const float* __restrict__ useq, const float* __restrict__ xGz0,
                  const float* __restrict__ gW1, const float* __restrict__ gb1,
                  const float* __restrict__ gW2, const float* __restrict__ gb2,
                  const float* __restrict__ gW3, const float* __restrict__ gb3,
                  float* __restrict__ out, int T) {
    extern __shared__ char smem_raw[];
    Smem& S = *reinterpret_cast<Smem*>(smem_raw);

    const int tid  = threadIdx.x;
    const int wid  = tid >> 5;
    const int lam  = tid & 31;
    const int rl   = lam & 7;          // row within warp
    const int cg   = lam >> 3;         // col group (16 cols)
    const int jc   = cg * 16;          // col base
    const int rown = wid * 8 + rl;     // CTA-local row
    const bool own = (cg == 0);

    // ---- CTA-shared weights (f16 dense, f32 W3) ----
    for (int i = tid; i < 50 * 64; i += NT) S.W1h[i] = __float2half(gW1[i]);
    for (int i = tid; i < 64 * 64; i += NT) S.W2h[i] = __float2half(gW2[i]);
    for (int i = tid; i < 64 * 8;  i += NT) S.W3[i]  = gW3[i];

    // bias f16x2 col pairs for this lane's 16 columns
    uint32_t bb1h[8], bb2h[8];
#pragma unroll
    for (int q = 0; q < 8; q++) {
        bb1h[q] = pack_h2(gb1[jc + 2 * q], gb1[jc + 2 * q + 1]);
        bb2h[q] = pack_h2(gb2[jc + 2 * q], gb2[jc + 2 * q + 1]);
    }

    const long gr = (long)blockIdx.x * BC + rown;
    float* qrow = S.Q + rown * 33;
    uint32_t* xcol = S.Xd + rown;            // stride 64 per k
    uint32_t* hrow = S.Hd + rown * 68;

    float xG[8], xcur[8], kacc[8], up[8], b3r[8];
    float u0 = 0.f, u1 = 0.f;
#pragma unroll
    for (int c = 0; c < 8; c++) { xG[c] = 0.f; xcur[c] = 0.f; kacc[c] = 0.f; up[c] = 0.f; b3r[c] = 0.f; }

    if (own) {
        const float* x0 = xGz0 + gr * 48;
#pragma unroll
        for (int c = 0; c < 8; c++) xG[c] = x0[c];
#pragma unroll
        for (int m = 0; m < 4; m++)
#pragma unroll
            for (int c = 0; c < 8; c++) qrow[m * 8 + c] = x0[8 + 8 * m + c];
#pragma unroll
        for (int q = 0; q < 8; q++) up[q] = x0[40 + q];
#pragma unroll
        for (int c = 0; c < 8; c++) b3r[c] = gb3[c];
        // initial X (dup f16x2 words)
#pragma unroll
        for (int k = 0; k < 48; k++) xcol[k * 64] = pack_h2(x0[k], x0[k]);
        u0 = useq[gr * T * 2 + 0];
        u1 = useq[gr * T * 2 + 1];
        xcol[48 * 64] = pack_h2(u0, u0);
        xcol[49 * 64] = pack_h2(u1, u1);
        xcol[50 * 64] = 0u;
        xcol[51 * 64] = 0u;
    }
    __syncthreads();

#pragma unroll 1
    for (int t = 0; t < T; t++) {
        if (own) {   // y_t = xG (pre-update)
            float* op = out + (gr * T + t) * 8;
            *(float4*)(op)     = make_float4(xG[0], xG[1], xG[2], xG[3]);
            *(float4*)(op + 4) = make_float4(xG[4], xG[5], xG[6], xG[7]);
        }
        __syncwarp();

#pragma unroll 1
        for (int s = 0; s < 4; s++) {
            // ---- dense1 (HFMA2): Xd -> Hd ----
            {
                uint32_t a[8];
#pragma unroll
                for (int q = 0; q < 8; q++) a[q] = bb1h[q];
                const __half* w = S.W1h + jc;
#pragma unroll 10
                for (int k = 0; k < 50; k++) {
                    const uint32_t xa = xcol[k * 64];       // {v,v}
                    const uint4 w0 = *(const uint4*)(w + k * 64);
                    const uint4 w1 = *(const uint4*)(w + k * 64 + 8);
                    HFMA2(a[0], xa, w0.x, a[0]);
                    HFMA2(a[1], xa, w0.y, a[1]);
                    HFMA2(a[2], xa, w0.z, a[2]);
                    HFMA2(a[3], xa, w0.w, a[3]);
                    HFMA2(a[4], xa, w1.x, a[4]);
                    HFMA2(a[5], xa, w1.y, a[5]);
                    HFMA2(a[6], xa, w1.z, a[6]);
                    HFMA2(a[7], xa, w1.w, a[7]);
                }
                // tanh + dup-split {j,j+1} -> {j,j},{j+1,j+1}, store to Hd
#pragma unroll
                for (int q = 0; q < 8; q++) {
                    const uint32_t tq = tanh2h(a[q]);
                    uint32_t lo, hi;
                    PRMT(lo, tq, tq, 0x1010);
                    PRMT(hi, tq, tq, 0x3232);
                    hrow[jc + 2 * q]     = lo;
                    hrow[jc + 2 * q + 1] = hi;
                }
            }
            __syncwarp();

            // ---- dense2 (HFMA2): Hd -> regs ----
            uint32_t a[8];
#pragma unroll
            for (int q = 0; q < 8; q++) a[q] = bb2h[q];
            {
                const __half* w = S.W2h + jc;
#pragma unroll 8
                for (int k = 0; k < 64; k++) {
                    const uint32_t xa = hrow[k];
                    const uint4 w0 = *(const uint4*)(w + k * 64);
                    const uint4 w1 = *(const uint4*)(w + k * 64 + 8);
                    HFMA2(a[0], xa, w0.x, a[0]);
                    HFMA2(a[1], xa, w0.y, a[1]);
                    HFMA2(a[2], xa, w0.z, a[2]);
                    HFMA2(a[3], xa, w0.w, a[3]);
                    HFMA2(a[4], xa, w1.x, a[4]);
                    HFMA2(a[5], xa, w1.y, a[5]);
                    HFMA2(a[6], xa, w1.z, a[6]);
                    HFMA2(a[7], xa, w1.w, a[7]);
                }
            }

            // ---- fused L3 (f32): partial over this lane's 16 k values ----
            ull c4[4];
            c4[0] = 0ull; c4[1] = 0ull; c4[2] = 0ull; c4[3] = 0ull;
#pragma unroll
            for (int q = 0; q < 8; q++) {
                const uint32_t tq = tanh2h(a[q]);
                float f0, f1;
                unpack_h2(f0, f1, tq);
                const int k0 = jc + 2 * q;
                ull x0p, x1p;
                PACK2(x0p, f0, f0);
                PACK2(x1p, f1, f1);
                const ull* w0 = (const ull*)(S.W3 + k0 * 8);
                const ulonglong2 wa0 = *(const ulonglong2*)(w0);
                const ulonglong2 wb0 = *(const ulonglong2*)(w0 + 2);
                const ulonglong2 wa1 = *(const ulonglong2*)(w0 + 4);
                const ulonglong2 wb1 = *(const ulonglong2*)(w0 + 6);
                FMA2(c4[0], x0p, wa0.x, c4[0]);
                FMA2(c4[1], x0p, wa0.y, c4[1]);
                FMA2(c4[2], x0p, wb0.x, c4[2]);
                FMA2(c4[3], x0p, wb0.y, c4[3]);
                FMA2(c4[0], x1p, wa1.x, c4[0]);
                FMA2(c4[1], x1p, wa1.y, c4[1]);
                FMA2(c4[2], x1p, wb1.x, c4[2]);
                FMA2(c4[3], x1p, wb1.y, c4[3]);
            }
            // butterfly across the 4 cg lanes (stride 8, 16)
#pragma unroll
            for (int m = 8; m <= 16; m <<= 1) {
#pragma unroll
                for (int j = 0; j < 4; j++) {
                    const ull o = __shfl_xor_sync(0xffffffffu, c4[j], m);
                    ull r;
                    asm("add.rn.f32x2 %0, %1, %2;" : "=l"(r) : "l"(c4[j]), "l"(o));
                    c4[j] = r;
                }
            }

            // ---- owner epilogue: fnn + fg + RK4 + X rebuild ----
            if (own) {
                float fnn[8];
                UNPACK2(fnn[0], fnn[1], c4[0]);
                UNPACK2(fnn[2], fnn[3], c4[1]);
                UNPACK2(fnn[4], fnn[5], c4[2]);
                UNPACK2(fnn[6], fnn[7], c4[3]);
#pragma unroll
                for (int c = 0; c < 8; c++) fnn[c] += b3r[c];

                float g[8];
                fg_eval((s == 0) ? xG : xcur, u0, u1, g);
                float kv[8];
#pragma unroll
                for (int c = 0; c < 8; c++) kv[c] = g[c] + fnn[c];

                if (s == 0) {
#pragma unroll
                    for (int c = 0; c < 8; c++) {
                        kacc[c] = kv[c];
                        xcur[c] = xG[c] + 0.005f * kv[c];
                    }
                    // zi (midpoints) -> X k=8..39
#pragma unroll
                    for (int m = 0; m < 4; m++) {
                        const float* qa = qrow + ((t + m) & 3) * 8;
                        const float* qb = qrow + ((t + m + 1) & 3) * 8;
#pragma unroll
                        for (int c = 0; c < 8; c++) {
                            const float nb = (m < 3) ? qb[c] : xG[c];
                            const float z = 0.5f * (qa[c] + nb);
                            xcol[(8 + m * 8 + c) * 64] = pack_h2(z, z);
                        }
                    }
                } else if (s == 1) {
#pragma unroll
                    for (int c = 0; c < 8; c++) {
                        kacc[c] += 2.0f * kv[c];
                        xcur[c] = xG[c] + 0.005f * kv[c];
                    }
                } else if (s == 2) {
#pragma unroll
                    for (int c = 0; c < 8; c++) {
                        kacc[c] += 2.0f * kv[c];
                        xcur[c] = xG[c] + 0.01f * kv[c];
                    }
                    // zs = [ypseq[1:4], xG] -> X k=8..39
#pragma unroll
                    for (int m = 0; m < 4; m++) {
                        const float* qb = qrow + ((t + m + 1) & 3) * 8;
#pragma unroll
                        for (int c = 0; c < 8; c++) {
                            const float z = (m < 3) ? qb[c] : xG[c];
                            xcol[(8 + m * 8 + c) * 64] = pack_h2(z, z);
                        }
                    }
                } else {
#pragma unroll
                    for (int c = 0; c < 8; c++) kacc[c] += kv[c];
                    float xnew[8];
#pragma unroll
                    for (int c = 0; c < 8; c++)
                        xnew[c] = xG[c] + (0.01f / 6.0f) * kacc[c];
                    {
                        float* qo = qrow + (t & 3) * 8;
#pragma unroll
                        for (int c = 0; c < 8; c++) qo[c] = xG[c];
                    }
                    // ypseq_{t+1} -> X k=8..39
#pragma unroll
                    for (int m = 0; m < 4; m++) {
                        const float* qn = qrow + ((t + 1 + m) & 3) * 8;
#pragma unroll
                        for (int c = 0; c < 8; c++)
                            xcol[(8 + m * 8 + c) * 64] = pack_h2(qn[c], qn[c]);
                    }
                    // upseq shift + new u
#pragma unroll
                    for (int q = 0; q < 6; q++) up[q] = up[q + 2];
                    up[6] = u0; up[7] = u1;
#pragma unroll
                    for (int q = 0; q < 8; q++)
                        xcol[(40 + q) * 64] = pack_h2(up[q], up[q]);
                    if (t + 1 < T) {
                        u0 = useq[(gr * T + t + 1) * 2 + 0];
                        u1 = useq[(gr * T + t + 1) * 2 + 1];
                    }
                    xcol[48 * 64] = pack_h2(u0, u0);
                    xcol[49 * 64] = pack_h2(u1, u1);
#pragma unroll
                    for (int c = 0; c < 8; c++) xG[c] = xnew[c];
                }
                // substep x -> X k=0..7
                const float* xw = (s == 3) ? xG : xcur;
#pragma unroll
                for (int c = 0; c < 8; c++)
                    xcol[c * 64] = pack_h2(xw[c], xw[c]);
            }
            __syncwarp();
        }
    }
}

// ---------------------------------------------------------------------------
extern "C" void kernel_launch(void* const* d_in, const int* in_sizes, int n_in,
                              void* d_out, int out_size) {
    const float* useq = (const float*)d_in[0];
    const float* xGz0 = (const float*)d_in[1];
    const float* W1   = (const float*)d_in[2];
    const float* b1   = (const float*)d_in[3];
    const float* W2   = (const float*)d_in[4];
    const float* b2   = (const float*)d_in[5];
    const float* W3   = (const float*)d_in[6];
    const float* b3   = (const float*)d_in[7];
    float* out = (float*)d_out;

    const int B = in_sizes[1] / 48;
    const int T = in_sizes[0] / (B * 2);

    const int smem = (int)sizeof(Smem);
    cudaFuncSetAttribute(cstr_flash_kernel,
                         cudaFuncAttributeMaxDynamicSharedMemorySize, smem);
    cstr_flash_kernel<<<B / BC, NT, smem>>>(useq, xGz0, W1, b1, W2, b2, W3, b3,
                                            out, T);
}

// round 17
// speedup vs baseline: 1.6093x; 1.0802x over previous
#include <cuda_runtime.h>
#include <cuda_fp16.h>
#include <math.h>
#include <cstdint>

#define NT 256
#define BC 64
#define XPI 60     // Xd row pitch (u32): 60 mod 32 = 28 -> 8-row bases distinct
#define HPI 68     // Hd row pitch (u32): 68 mod 32 = 4  -> 8-row bases distinct
typedef unsigned long long ull;

#define FMA2(d, a, b, c) \
    asm("fma.rn.f32x2 %0, %1, %2, %3;" : "=l"(d) : "l"(a), "l"(b), "l"(c))
#define PACK2(d, lo, hi) \
    asm("mov.b64 %0, {%1, %2};" : "=l"(d) : "f"(lo), "f"(hi))
#define UNPACK2(lo, hi, v) \
    asm("mov.b64 {%0, %1}, %2;" : "=f"(lo), "=f"(hi) : "l"(v))
#define HFMA2(d, a, b, c) \
    asm("fma.rn.f16x2 %0, %1, %2, %3;" : "=r"(d) : "r"(a), "r"(b), "r"(c))
#define PRMT(d, a, b, sel) \
    asm("prmt.b32 %0, %1, %2, %3;" : "=r"(d) : "r"(a), "r"(b), "n"(sel))

__device__ __forceinline__ uint32_t tanh2h(uint32_t h) {
    asm("tanh.approx.f16x2 %0, %0;" : "+r"(h));
    return h;
}
__device__ __forceinline__ void unpack_h2(float& lo, float& hi, uint32_t h) {
    asm("{ .reg .f16 l, u; mov.b32 {l, u}, %2;"
        " cvt.f32.f16 %0, l; cvt.f32.f16 %1, u; }"
        : "=f"(lo), "=f"(hi) : "r"(h));
}
__device__ __forceinline__ uint32_t pack_h2(float lo, float hi) {
    uint32_t h;
    asm("cvt.rn.f16x2.f32 %0, %1, %2;" : "=r"(h) : "f"(hi), "f"(lo));
    return h;
}
__device__ __forceinline__ float rcp_fast(float x) {
    float y; asm("rcp.approx.f32 %0, %1;" : "=f"(y) : "f"(x)); return y;
}
__device__ __forceinline__ float sqrt_fast(float x) {
    float y; asm("sqrt.approx.f32 %0, %1;" : "=f"(y) : "f"(x)); return y;
}

// ---------------------------------------------------------------------------
// Row-major activations (dup f16x2 words) so a lane fetches 4 k's per LDS.128.
// ---------------------------------------------------------------------------
struct __align__(16) Smem {
    float    W3[64 * 8];      // f32 [k][j]
    float    Q[64 * 33];      // ypseq circular queue per row
    uint32_t Xd[64 * XPI];    // MLP input, dup f16x2 {v,v}, [row][k] (52 used)
    uint32_t Hd[64 * HPI];    // hidden1, dup f16x2, [row][k]
    __half   W1h[52 * 64];    // f16 [k][j], rows 50,51 zero
    __half   W2h[64 * 64];    // f16 [k][j]
};

// ---------------------------------------------------------------------------
// Grey-box CSTR+flash RHS (scaled); approx rcp/sqrt/exp.
// ---------------------------------------------------------------------------
__device__ __forceinline__ void fg_eval(const float* x, float u0f, float u1f,
                                        float* g) {
    const float Hr  = 0.3f * x[0] + 0.7f;
    const float CAr = 0.2f * x[1] + 0.5f;
    const float CBr = 0.2f * x[2] + 0.5f;
    const float Tr  = 5.0f * x[3] + 310.0f;
    const float Hb  = 0.3f * x[4] + 0.7f;
    const float CAb = 0.2f * x[5] + 0.5f;
    const float CBb = 0.2f * x[6] + 0.5f;
    const float Tb  = 5.0f * x[7] + 310.0f;
    const float Fu  = 0.1f  * u0f + 1.0f;
    const float Du  = 0.05f * u1f + 0.5f;

    const float rden = rcp_fast(3.5f * CAb + 1.1f * CBb);
    const float CAd = 3.5f * CAb * rden;
    const float CBd = 1.1f * CBb * rden;
    const float Fr  = sqrt_fast(Hr);
    const float Fb  = sqrt_fast(Hb);
    const float k1c = 20000.0f * __expf(-3000.0f * rcp_fast(Tr));
    const float r1  = k1c * CAr;
    const float rHr = rcp_fast(Hr);
    const float rHb = rcp_fast(Hb);

    g[0] = (Fu + Du - Fr) * (1.0f / 0.3f);
    g[1] = ((Fu * (1.0f - CAr) + Du * (CAd - CAr)) * rHr - r1) * (1.0f / 0.2f);
    g[2] = ((-Fu * CBr + Du * (CBd - CBr)) * rHr + r1) * (1.0f / 0.2f);
    g[3] = ((Fu * (320.0f - Tr) + Du * (310.0f - Tr)) * rHr
            - (200.0f / 15.0f) * rHr + r1 * (10.0f / 15.0f)) * (1.0f / 5.0f);
    g[4] = (Fr - Fb - Du) * (1.0f / 0.3f);
    g[5] = ((Fr * (CAr - CAb) + Du * (CAb - CAd)) * rHb) * (1.0f / 0.2f);
    g[6] = ((Fr * (CBr - CBb) + Du * (CBb - CBd)) * rHb) * (1.0f / 0.2f);
    g[7] = (Fr * (Tr - Tb) * rHb + (200.0f / 15.0f) * rHb) * (1.0f / 5.0f);
}

// ---------------------------------------------------------------------------
// Persistent kernel: CTA = 64 rows, 256 threads (8 warps, 2/SMSP), grid 128.
// Warp wid owns rows [8*wid, 8*wid+8) END-TO-END. Lane: row = lam&7,
// col group cg = lam>>3 (16 cols). No __syncthreads in the main loop.
// ---------------------------------------------------------------------------
__global__ void __launch_bounds__(NT, 1)
cstr_flash_kernel(const float* __restrict__ useq, const float* __restrict__ xGz0,
                  const float* __restrict__ gW1, const float* __restrict__ gb1,
                  const float* __restrict__ gW2, const float* __restrict__ gb2,
                  const float* __restrict__ gW3, const float* __restrict__ gb3,
                  float* __restrict__ out, int T) {
    extern __shared__ char smem_raw[];
    Smem& S = *reinterpret_cast<Smem*>(smem_raw);

    const int tid  = threadIdx.x;
    const int wid  = tid >> 5;
    const int lam  = tid & 31;
    const int rl   = lam & 7;
    const int cg   = lam >> 3;
    const int jc   = cg * 16;
    const int rown = wid * 8 + rl;
    const bool own = (cg == 0);

    // ---- CTA-shared weights ----
    for (int i = tid; i < 52 * 64; i += NT)
        S.W1h[i] = (i < 50 * 64) ? __float2half(gW1[i]) : __half(0.0f);
    for (int i = tid; i < 64 * 64; i += NT) S.W2h[i] = __float2half(gW2[i]);
    for (int i = tid; i < 64 * 8;  i += NT) S.W3[i]  = gW3[i];

    // bias f16x2 col pairs for this lane's 16 columns
    uint32_t bb1h[8], bb2h[8];
#pragma unroll
    for (int q = 0; q < 8; q++) {
        bb1h[q] = pack_h2(gb1[jc + 2 * q], gb1[jc + 2 * q + 1]);
        bb2h[q] = pack_h2(gb2[jc + 2 * q], gb2[jc + 2 * q + 1]);
    }

    const long gr = (long)blockIdx.x * BC + rown;
    float* qrow = S.Q + rown * 33;
    uint32_t* xrow = S.Xd + rown * XPI;
    uint32_t* hrow = S.Hd + rown * HPI;

    float xG[8], xcur[8], kacc[8], up[8], b3r[8];
    float u0 = 0.f, u1 = 0.f;
#pragma unroll
    for (int c = 0; c < 8; c++) { xG[c] = 0.f; xcur[c] = 0.f; kacc[c] = 0.f; up[c] = 0.f; b3r[c] = 0.f; }

    if (own) {
        const float* x0 = xGz0 + gr * 48;
#pragma unroll
        for (int c = 0; c < 8; c++) xG[c] = x0[c];
#pragma unroll
        for (int m = 0; m < 4; m++)
#pragma unroll
            for (int c = 0; c < 8; c++) qrow[m * 8 + c] = x0[8 + 8 * m + c];
#pragma unroll
        for (int q = 0; q < 8; q++) up[q] = x0[40 + q];
#pragma unroll
        for (int c = 0; c < 8; c++) b3r[c] = gb3[c];
#pragma unroll
        for (int k = 0; k < 48; k++) xrow[k] = pack_h2(x0[k], x0[k]);
        u0 = useq[gr * T * 2 + 0];
        u1 = useq[gr * T * 2 + 1];
        xrow[48] = pack_h2(u0, u0);
        xrow[49] = pack_h2(u1, u1);
        xrow[50] = 0u;
        xrow[51] = 0u;
    }
    __syncthreads();

#pragma unroll 1
    for (int t = 0; t < T; t++) {
        if (own) {   // y_t = xG (pre-update)
            float* op = out + (gr * T + t) * 8;
            *(float4*)(op)     = make_float4(xG[0], xG[1], xG[2], xG[3]);
            *(float4*)(op + 4) = make_float4(xG[4], xG[5], xG[6], xG[7]);
        }
        __syncwarp();

#pragma unroll 1
        for (int s = 0; s < 4; s++) {
            // ---- dense1 (HFMA2): Xd -> Hd; x fetched 4 k's per LDS.128 ----
            {
                uint32_t a[8];
#pragma unroll
                for (int q = 0; q < 8; q++) a[q] = bb1h[q];
                const __half* w = S.W1h + jc;
#pragma unroll
                for (int k0 = 0; k0 < 52; k0 += 4) {
                    const uint4 xq = *(const uint4*)(xrow + k0);
#pragma unroll
                    for (int d = 0; d < 4; d++) {
                        const uint32_t xa = (d == 0) ? xq.x : (d == 1) ? xq.y
                                          : (d == 2) ? xq.z : xq.w;
                        const __half* wk = w + (k0 + d) * 64;
                        const uint4 w0 = *(const uint4*)(wk);
                        const uint4 w1 = *(const uint4*)(wk + 8);
                        HFMA2(a[0], xa, w0.x, a[0]);
                        HFMA2(a[1], xa, w0.y, a[1]);
                        HFMA2(a[2], xa, w0.z, a[2]);
                        HFMA2(a[3], xa, w0.w, a[3]);
                        HFMA2(a[4], xa, w1.x, a[4]);
                        HFMA2(a[5], xa, w1.y, a[5]);
                        HFMA2(a[6], xa, w1.z, a[6]);
                        HFMA2(a[7], xa, w1.w, a[7]);
                    }
                }
                // tanh + dup-split, store 16 dup words as 4 uint4
                uint32_t hv[16];
#pragma unroll
                for (int q = 0; q < 8; q++) {
                    const uint32_t tq = tanh2h(a[q]);
                    PRMT(hv[2 * q],     tq, tq, 0x1010);
                    PRMT(hv[2 * q + 1], tq, tq, 0x3232);
                }
#pragma unroll
                for (int i = 0; i < 4; i++)
                    *(uint4*)(hrow + jc + 4 * i) =
                        make_uint4(hv[4 * i], hv[4 * i + 1],
                                   hv[4 * i + 2], hv[4 * i + 3]);
            }
            __syncwarp();

            // ---- dense2 (HFMA2): Hd -> regs; x fetched 4 k's per LDS.128 ----
            uint32_t a[8];
#pragma unroll
            for (int q = 0; q < 8; q++) a[q] = bb2h[q];
            {
                const __half* w = S.W2h + jc;
#pragma unroll
                for (int k0 = 0; k0 < 64; k0 += 4) {
                    const uint4 xq = *(const uint4*)(hrow + k0);
#pragma unroll
                    for (int d = 0; d < 4; d++) {
                        const uint32_t xa = (d == 0) ? xq.x : (d == 1) ? xq.y
                                          : (d == 2) ? xq.z : xq.w;
                        const __half* wk = w + (k0 + d) * 64;
                        const uint4 w0 = *(const uint4*)(wk);
                        const uint4 w1 = *(const uint4*)(wk + 8);
                        HFMA2(a[0], xa, w0.x, a[0]);
                        HFMA2(a[1], xa, w0.y, a[1]);
                        HFMA2(a[2], xa, w0.z, a[2]);
                        HFMA2(a[3], xa, w0.w, a[3]);
                        HFMA2(a[4], xa, w1.x, a[4]);
                        HFMA2(a[5], xa, w1.y, a[5]);
                        HFMA2(a[6], xa, w1.z, a[6]);
                        HFMA2(a[7], xa, w1.w, a[7]);
                    }
                }
            }

            // ---- fused L3 (f32): partial over this lane's 16 k values ----
            ull c4[4];
            c4[0] = 0ull; c4[1] = 0ull; c4[2] = 0ull; c4[3] = 0ull;
#pragma unroll
            for (int q = 0; q < 8; q++) {
                const uint32_t tq = tanh2h(a[q]);
                float f0, f1;
                unpack_h2(f0, f1, tq);
                const int k0 = jc + 2 * q;
                ull x0p, x1p;
                PACK2(x0p, f0, f0);
                PACK2(x1p, f1, f1);
                const ull* w0 = (const ull*)(S.W3 + k0 * 8);
                const ulonglong2 wa0 = *(const ulonglong2*)(w0);
                const ulonglong2 wb0 = *(const ulonglong2*)(w0 + 2);
                const ulonglong2 wa1 = *(const ulonglong2*)(w0 + 4);
                const ulonglong2 wb1 = *(const ulonglong2*)(w0 + 6);
                FMA2(c4[0], x0p, wa0.x, c4[0]);
                FMA2(c4[1], x0p, wa0.y, c4[1]);
                FMA2(c4[2], x0p, wb0.x, c4[2]);
                FMA2(c4[3], x0p, wb0.y, c4[3]);
                FMA2(c4[0], x1p, wa1.x, c4[0]);
                FMA2(c4[1], x1p, wa1.y, c4[1]);
                FMA2(c4[2], x1p, wb1.x, c4[2]);
                FMA2(c4[3], x1p, wb1.y, c4[3]);
            }
            // butterfly across the 4 cg lanes (stride 8, 16)
#pragma unroll
            for (int m = 8; m <= 16; m <<= 1) {
#pragma unroll
                for (int j = 0; j < 4; j++) {
                    const ull o = __shfl_xor_sync(0xffffffffu, c4[j], m);
                    ull r;
                    asm("add.rn.f32x2 %0, %1, %2;" : "=l"(r) : "l"(c4[j]), "l"(o));
                    c4[j] = r;
                }
            }

            // ---- owner epilogue: fnn + fg + RK4 + X rebuild ----
            if (own) {
                float fnn[8];
                UNPACK2(fnn[0], fnn[1], c4[0]);
                UNPACK2(fnn[2], fnn[3], c4[1]);
                UNPACK2(fnn[4], fnn[5], c4[2]);
                UNPACK2(fnn[6], fnn[7], c4[3]);
#pragma unroll
                for (int c = 0; c < 8; c++) fnn[c] += b3r[c];

                float g[8];
                fg_eval((s == 0) ? xG : xcur, u0, u1, g);
                float kv[8];
#pragma unroll
                for (int c = 0; c < 8; c++) kv[c] = g[c] + fnn[c];

                if (s == 0) {
#pragma unroll
                    for (int c = 0; c < 8; c++) {
                        kacc[c] = kv[c];
                        xcur[c] = xG[c] + 0.005f * kv[c];
                    }
                    // zi (midpoints) -> X k=8..39
#pragma unroll
                    for (int m = 0; m < 4; m++) {
                        const float* qa = qrow + ((t + m) & 3) * 8;
                        const float* qb = qrow + ((t + m + 1) & 3) * 8;
#pragma unroll
                        for (int c = 0; c < 8; c++) {
                            const float nb = (m < 3) ? qb[c] : xG[c];
                            const float z = 0.5f * (qa[c] + nb);
                            xrow[8 + m * 8 + c] = pack_h2(z, z);
                        }
                    }
                } else if (s == 1) {
#pragma unroll
                    for (int c = 0; c < 8; c++) {
                        kacc[c] += 2.0f * kv[c];
                        xcur[c] = xG[c] + 0.005f * kv[c];
                    }
                } else if (s == 2) {
#pragma unroll
                    for (int c = 0; c < 8; c++) {
                        kacc[c] += 2.0f * kv[c];
                        xcur[c] = xG[c] + 0.01f * kv[c];
                    }
                    // zs = [ypseq[1:4], xG] -> X k=8..39
#pragma unroll
                    for (int m = 0; m < 4; m++) {
                        const float* qb = qrow + ((t + m + 1) & 3) * 8;
#pragma unroll
                        for (int c = 0; c < 8; c++) {
                            const float z = (m < 3) ? qb[c] : xG[c];
                            xrow[8 + m * 8 + c] = pack_h2(z, z);
                        }
                    }
                } else {
#pragma unroll
                    for (int c = 0; c < 8; c++) kacc[c] += kv[c];
                    float xnew[8];
#pragma unroll
                    for (int c = 0; c < 8; c++)
                        xnew[c] = xG[c] + (0.01f / 6.0f) * kacc[c];
                    {
                        float* qo = qrow + (t & 3) * 8;
#pragma unroll
                        for (int c = 0; c < 8; c++) qo[c] = xG[c];
                    }
                    // ypseq_{t+1} -> X k=8..39
#pragma unroll
                    for (int m = 0; m < 4; m++) {
                        const float* qn = qrow + ((t + 1 + m) & 3) * 8;
#pragma unroll
                        for (int c = 0; c < 8; c++)
                            xrow[8 + m * 8 + c] = pack_h2(qn[c], qn[c]);
                    }
                    // upseq shift + new u
#pragma unroll
                    for (int q = 0; q < 6; q++) up[q] = up[q + 2];
                    up[6] = u0; up[7] = u1;
#pragma unroll
                    for (int q = 0; q < 8; q++)
                        xrow[40 + q] = pack_h2(up[q], up[q]);
                    if (t + 1 < T) {
                        u0 = useq[(gr * T + t + 1) * 2 + 0];
                        u1 = useq[(gr * T + t + 1) * 2 + 1];
                    }
                    xrow[48] = pack_h2(u0, u0);
                    xrow[49] = pack_h2(u1, u1);
#pragma unroll
                    for (int c = 0; c < 8; c++) xG[c] = xnew[c];
                }
                // substep x -> X k=0..7
                const float* xw = (s == 3) ? xG : xcur;
#pragma unroll
                for (int c = 0; c < 8; c++)
                    xrow[c] = pack_h2(xw[c], xw[c]);
            }
            __syncwarp();
        }
    }
}

// ---------------------------------------------------------------------------
extern "C" void kernel_launch(void* const* d_in, const int* in_sizes, int n_in,
                              void* d_out, int out_size) {
    const float* useq = (const float*)d_in[0];
    const float* xGz0 = (const float*)d_in[1];
    const float* W1   = (const float*)d_in[2];
    const float* b1   = (const float*)d_in[3];
    const float* W2   = (const float*)d_in[4];
    const float* b2   = (const float*)d_in[5];
    const float* W3   = (const float*)d_in[6];
    const float* b3   = (const float*)d_in[7];
    float* out = (float*)d_out;

    const int B = in_sizes[1] / 48;
    const int T = in_sizes[0] / (B * 2);

    const int smem = (int)sizeof(Smem);
    cudaFuncSetAttribute(cstr_flash_kernel,
                         cudaFuncAttributeMaxDynamicSharedMemorySize, smem);
    cstr_flash_kernel<<<B / BC, NT, smem>>>(useq, xGz0, W1, b1, W2, b2, W3, b3,
                                            out, T);
}